// round 5
// baseline (speedup 1.0000x reference)
#include <cuda_runtime.h>
#include <math_constants.h>

// Problem constants
#define N_BATCH 4
#define C_CH    128
#define S_FR    31
#define HW      704           // 32*22
#define SHW     21824         // 31*704
#define NS      120           // 4*(31-1)
#define NPIX    87296         // 4*31*704
#define NG4     21824         // NPIX/4 float4 pixel-groups
#define TOPK    16
#define NB      128           // denominator bins (power of 2)
#define LOG2E   1.4426950408889634f
#define LN2F    0.6931471805599453f

// Scratch (device globals — no allocation allowed)
__device__ float  g_X0[NS * HW];        // a values
__device__ float  g_BL[NS * HW];        // b * log2e (order-preserving)
__device__ float  g_TB[NS * 32];        // [0..15] top desc, [16..31] bottom asc
__device__ float4 g_BINS[NS * NB];      // per row: (S0, S1, S2/2, S3/6) per bin
__device__ float2 g_ROW[NS];            // per row: (lo, W)

__device__ __forceinline__ float ex2(float x) {
    float r;
    asm("ex2.approx.f32 %0, %1;" : "=f"(r) : "f"(x));
    return r;
}

// ---------------------------------------------------------------------------
// Kernel A: channel contraction. Each thread: 4 consecutive pixels (float4)
// x 32 channels (split-C 4). LDG.128, 8-deep batches -> 4KB in flight / warp.
// Block: 128 threads = 32 float4-groups x 4 quarters. Grid 682.
// ---------------------------------------------------------------------------
__global__ void __launch_bounds__(128)
kA(const float* __restrict__ x,
   const float* __restrict__ w1, const float* __restrict__ b1,
   const float* __restrict__ w2, const float* __restrict__ b2) {
    __shared__ float sw1[C_CH], sw2[C_CH];
    __shared__ float4 p1s[4][32], p2s[4][32];
    int tid = threadIdx.x;          // 0..127
    sw1[tid] = w1[tid];
    sw2[tid] = w2[tid];
    __syncthreads();

    int quarter = tid >> 5;         // 0..3  (one warp per quarter)
    int g       = tid & 31;
    int p4 = blockIdx.x * 32 + g;   // NG4 = 32*682 exactly
    int n  = p4 / (SHW / 4);
    int q4 = p4 - n * (SHW / 4);
    int q  = q4 * 4;

    const float4* xp = reinterpret_cast<const float4*>(
        x + (size_t)n * (C_CH * SHW) + (size_t)(quarter * 32) * SHW) + q4;
    const float* pw1 = sw1 + quarter * 32;
    const float* pw2 = sw2 + quarter * 32;

    float4 a1 = make_float4(0.f, 0.f, 0.f, 0.f);
    float4 a2 = make_float4(0.f, 0.f, 0.f, 0.f);
#pragma unroll
    for (int cb = 0; cb < 32; cb += 8) {
        float4 v[8];
#pragma unroll
        for (int u = 0; u < 8; u++) v[u] = xp[(size_t)(cb + u) * (SHW / 4)];
#pragma unroll
        for (int u = 0; u < 8; u++) {
            float c1 = pw1[cb + u], c2 = pw2[cb + u];
            a1.x = fmaf(v[u].x, c1, a1.x);  a2.x = fmaf(v[u].x, c2, a2.x);
            a1.y = fmaf(v[u].y, c1, a1.y);  a2.y = fmaf(v[u].y, c2, a2.y);
            a1.z = fmaf(v[u].z, c1, a1.z);  a2.z = fmaf(v[u].z, c2, a2.z);
            a1.w = fmaf(v[u].w, c1, a1.w);  a2.w = fmaf(v[u].w, c2, a2.w);
        }
    }
    p1s[quarter][g] = a1;
    p2s[quarter][g] = a2;
    __syncthreads();

    if (quarter == 0) {
        float4 q1 = p1s[1][g], q2 = p1s[2][g], q3 = p1s[3][g];
        float4 r1 = p2s[1][g], r2 = p2s[2][g], r3 = p2s[3][g];
        float bb1 = b1[0], bb2 = b2[0];
        float4 y1 = make_float4((a1.x + q1.x) + (q2.x + q3.x) + bb1,
                                (a1.y + q1.y) + (q2.y + q3.y) + bb1,
                                (a1.z + q1.z) + (q2.z + q3.z) + bb1,
                                (a1.w + q1.w) + (q2.w + q3.w) + bb1);
        float4 y2 = make_float4(((a2.x + r1.x) + (r2.x + r3.x) + bb2) * LOG2E,
                                ((a2.y + r1.y) + (r2.y + r3.y) + bb2) * LOG2E,
                                ((a2.z + r1.z) + (r2.z + r3.z) + bb2) * LOG2E,
                                ((a2.w + r1.w) + (r2.w + r3.w) + bb2) * LOG2E);
        int f = q / HW;             // HW%4==0 -> whole group same frame
        int i = q - f * HW;
        if (f < S_FR - 1)
            *reinterpret_cast<float4*>(&g_X0[(n * (S_FR - 1) + f) * HW + i]) = y1;
        if (f >= 1)
            *reinterpret_cast<float4*>(&g_BL[(n * (S_FR - 1) + f - 1) * HW + i]) = y2;
    }
}

// ---------------------------------------------------------------------------
// Kernel B: per-row min/max + moment bins + top/bottom-16 selection.
// 256 threads/block, 120 blocks. warp0 iterative top-16 on sv,
// warp1 iterative bottom-16 on sv2 (separate copies; consumption-safe).
// ---------------------------------------------------------------------------
__global__ void kB() {
    __shared__ float sv[HW], sv2[HW];
    __shared__ float binS0[NB], binS1[NB], binS2[NB], binS3[NB];
    __shared__ float rmin[8], rmax[8];
    __shared__ float s_lo, s_W, s_invW;
    int r = blockIdx.x;
    int tid = threadIdx.x;   // 256
    int lane = tid & 31, wid = tid >> 5;

    float lmin = CUDART_INF_F, lmax = -CUDART_INF_F;
    for (int j = tid; j < HW; j += 256) {
        float v = g_BL[r * HW + j];
        sv[j] = v; sv2[j] = v;
        lmin = fminf(lmin, v);
        lmax = fmaxf(lmax, v);
    }
    if (tid < NB) { binS0[tid] = 0.f; binS1[tid] = 0.f; binS2[tid] = 0.f; binS3[tid] = 0.f; }
#pragma unroll
    for (int o = 16; o; o >>= 1) {
        lmin = fminf(lmin, __shfl_xor_sync(0xffffffffu, lmin, o));
        lmax = fmaxf(lmax, __shfl_xor_sync(0xffffffffu, lmax, o));
    }
    if (lane == 0) { rmin[wid] = lmin; rmax[wid] = lmax; }
    __syncthreads();
    if (tid == 0) {
        float lo = rmin[0], hi = rmax[0];
#pragma unroll
        for (int w = 1; w < 8; w++) { lo = fminf(lo, rmin[w]); hi = fmaxf(hi, rmax[w]); }
        float W = (hi - lo) * (1.0f / NB) + 1e-30f;
        s_lo = lo; s_W = W; s_invW = 1.0f / W;
        g_ROW[r] = make_float2(lo, W);
    }
    __syncthreads();

    {
        float lo = s_lo, W = s_W, invW = s_invW;
        for (int j = tid; j < HW; j += 256) {
            float v = sv[j];
            int m = (int)((v - lo) * invW);
            m = (m > NB - 1) ? NB - 1 : (m < 0 ? 0 : m);
            float d = v - fmaf((float)m + 0.5f, W, lo);
            atomicAdd(&binS0[m], 1.0f);
            atomicAdd(&binS1[m], d);
            atomicAdd(&binS2[m], 0.5f * d * d);
            atomicAdd(&binS3[m], (1.0f / 6.0f) * d * d * d);
        }
    }
    __syncthreads();
    if (tid < NB)
        g_BINS[r * NB + tid] = make_float4(binS0[tid], binS1[tid], binS2[tid], binS3[tid]);

    if (wid == 0) {
        for (int it = 0; it < TOPK; it++) {
            float lm = -CUDART_INF_F; int li = 0;
            for (int j = lane; j < HW; j += 32) {
                float v = sv[j];
                if (v > lm) { lm = v; li = j; }
            }
#pragma unroll
            for (int o = 16; o; o >>= 1) {
                float ov = __shfl_xor_sync(0xffffffffu, lm, o);
                int   oi = __shfl_xor_sync(0xffffffffu, li, o);
                if (ov > lm || (ov == lm && oi < li)) { lm = ov; li = oi; }
            }
            if (lane == 0) { g_TB[r * 32 + it] = lm; sv[li] = -CUDART_INF_F; }
            __syncwarp();
        }
    } else if (wid == 1) {
        for (int it = 0; it < TOPK; it++) {
            float lm = CUDART_INF_F; int li = 0;
            for (int j = lane; j < HW; j += 32) {
                float v = sv2[j];
                if (v < lm) { lm = v; li = j; }
            }
#pragma unroll
            for (int o = 16; o; o >>= 1) {
                float ov = __shfl_xor_sync(0xffffffffu, lm, o);
                int   oi = __shfl_xor_sync(0xffffffffu, li, o);
                if (ov < lm || (ov == lm && oi < li)) { lm = ov; li = oi; }
            }
            if (lane == 0) { g_TB[r * 32 + 16 + it] = lm; sv2[li] = CUDART_INF_F; }
            __syncwarp();
        }
    }
}

// ---------------------------------------------------------------------------
// Kernel C: denominator via geometric-chain over bins (FMA pipe),
// then exact top-k numerators. 11 chunks of 64 pixels per row.
// ---------------------------------------------------------------------------
__global__ void kC(float* __restrict__ out) {
    __shared__ float4 sb[NB];
    __shared__ float ssel[32];
    int r = blockIdx.x / 11;
    int chunk = blockIdx.x - r * 11;
    int tid = threadIdx.x;   // 64

    sb[tid]      = g_BINS[r * NB + tid];
    sb[tid + 64] = g_BINS[r * NB + 64 + tid];
    if (tid < 32) ssel[tid] = g_TB[r * 32 + tid];
    __syncthreads();

    int i = chunk * 64 + tid;
    float a = g_X0[r * HW + i];
    float2 rp = g_ROW[r];
    float lo = rp.x, W = rp.y;

    bool pos = (a >= 0.f);
    float msc = pos ? a * ssel[0] : a * ssel[16];
    float nm = -msc;
    int mask = pos ? (NB - 1) : 0;
    float cs = pos ? fmaf((float)NB - 0.5f, W, lo) : fmaf(0.5f, W, lo);

    float rho = ex2(-fabsf(a) * W);                 // <= 1, decaying chain
    float rho4 = rho * rho; rho4 *= rho4;
    float p0 = ex2(fmaf(a, cs, nm));
    float p1 = p0 * rho, p2 = p1 * rho, p3 = p2 * rho;
    float L = a * LN2F;

    float D0 = 0.f, D1 = 0.f, D2 = 0.f, D3 = 0.f;
#pragma unroll 4
    for (int m = 0; m < NB; m += 4) {
        float4 c0 = sb[(m + 0) ^ mask];
        float4 c1 = sb[(m + 1) ^ mask];
        float4 c2 = sb[(m + 2) ^ mask];
        float4 c3 = sb[(m + 3) ^ mask];
        D0 = fmaf(p0, fmaf(L, fmaf(L, fmaf(L, c0.w, c0.z), c0.y), c0.x), D0);
        D1 = fmaf(p1, fmaf(L, fmaf(L, fmaf(L, c1.w, c1.z), c1.y), c1.x), D1);
        D2 = fmaf(p2, fmaf(L, fmaf(L, fmaf(L, c2.w, c2.z), c2.y), c2.x), D2);
        D3 = fmaf(p3, fmaf(L, fmaf(L, fmaf(L, c3.w, c3.z), c3.y), c3.x), D3);
        p0 *= rho4; p1 *= rho4; p2 *= rho4; p3 *= rho4;
    }
    float rD = __frcp_rn((D0 + D1) + (D2 + D3));

    const float* sel = pos ? ssel : (ssel + 16);
    float v[TOPK];
#pragma unroll
    for (int k = 0; k < TOPK; k++)
        v[k] = ex2(fmaf(a, sel[k], nm)) * rD;

    // output: idx = i*16 + k ; k2 = i/44 (k-independent)
    int n  = r / (S_FR - 1);
    int sp = r - n * (S_FR - 1);
    int k2 = i / 44;
    int im = i - k2 * 44;
    float4* o = reinterpret_cast<float4*>(
        out + ((size_t)((n * TOPK + k2) * (S_FR - 1) + sp)) * HW + im * 16);
    o[0] = make_float4(v[0],  v[1],  v[2],  v[3]);
    o[1] = make_float4(v[4],  v[5],  v[6],  v[7]);
    o[2] = make_float4(v[8],  v[9],  v[10], v[11]);
    o[3] = make_float4(v[12], v[13], v[14], v[15]);
}

// ---------------------------------------------------------------------------
extern "C" void kernel_launch(void* const* d_in, const int* in_sizes, int n_in,
                              void* d_out, int out_size) {
    const float* x  = (const float*)d_in[0];
    const float* w1 = (const float*)d_in[1];
    const float* b1 = (const float*)d_in[2];
    const float* w2 = (const float*)d_in[3];
    const float* b2 = (const float*)d_in[4];
    float* out = (float*)d_out;

    kA<<<NG4 / 32, 128>>>(x, w1, b1, w2, b2);
    kB<<<NS, 256>>>();
    kC<<<NS * 11, 64>>>(out);
}

// round 6
// speedup vs baseline: 1.5548x; 1.5548x over previous
#include <cuda_runtime.h>
#include <math_constants.h>

// Problem constants
#define N_BATCH 4
#define C_CH    128
#define S_FR    31
#define HW      704           // 32*22
#define NS      120           // 4*(31-1)
#define NPIX    87296         // 4*31*704 (= 64*1364)
#define TOPK    16
#define NB      128           // denominator bins (power of 2)
#define NWARP   22            // 704/32
#define LOG2E   1.4426950408889634f
#define LN2F    0.6931471805599453f

// Scratch (device globals — no allocation allowed)
__device__ float g_X0[NS * HW];        // a values
__device__ float g_BL[NS * HW];        // b * log2e (order-preserving)

__device__ __forceinline__ float ex2(float x) {
    float r;
    asm("ex2.approx.f32 %0, %1;" : "=f"(r) : "f"(x));
    return r;
}

// ---------------------------------------------------------------------------
// Kernel A (R3 winner, verbatim): channel contraction, 2 threads per pixel.
// Block: 128 threads = 64 pixels x 2 channel halves.
// ---------------------------------------------------------------------------
__global__ void kA(const float* __restrict__ x,
                   const float* __restrict__ w1, const float* __restrict__ b1,
                   const float* __restrict__ w2, const float* __restrict__ b2) {
    __shared__ float sw1[C_CH], sw2[C_CH];
    __shared__ float r1s[64], r2s[64];
    int tid = threadIdx.x;          // 0..127
    sw1[tid] = w1[tid];
    sw2[tid] = w2[tid];
    __syncthreads();

    int half = tid >> 6;            // 0 or 1
    int px   = tid & 63;
    int p = blockIdx.x * 64 + px;   // NPIX = 64*1364 exactly
    int n = p / (S_FR * HW);
    int q = p - n * (S_FR * HW);
    int f = q / HW;
    int i = q - f * HW;

    const float* xp = x + (size_t)n * (C_CH * S_FR * HW)
                        + (size_t)(half * 64) * (S_FR * HW) + q;
    const float* pw1 = sw1 + half * 64;
    const float* pw2 = sw2 + half * 64;

    float y1a = 0.f, y1b = 0.f, y2a = 0.f, y2b = 0.f;
#pragma unroll
    for (int cb = 0; cb < 64; cb += 16) {
        float v[16];
#pragma unroll
        for (int u = 0; u < 16; u++) v[u] = xp[(cb + u) * (S_FR * HW)];
#pragma unroll
        for (int u = 0; u < 16; u += 2) {
            y1a = fmaf(v[u],     pw1[cb + u],     y1a);
            y2a = fmaf(v[u],     pw2[cb + u],     y2a);
            y1b = fmaf(v[u + 1], pw1[cb + u + 1], y1b);
            y2b = fmaf(v[u + 1], pw2[cb + u + 1], y2b);
        }
    }
    float y1 = y1a + y1b, y2 = y2a + y2b;

    if (half == 1) { r1s[px] = y1; r2s[px] = y2; }
    __syncthreads();
    if (half == 0) {
        y1 += r1s[px];
        y2 += r2s[px];
        if (f < S_FR - 1) g_X0[(n * (S_FR - 1) + f) * HW + i] = y1 + b1[0];
        if (f >= 1)       g_BL[(n * (S_FR - 1) + f - 1) * HW + i] = (y2 + b2[0]) * LOG2E;
    }
}

// ---------------------------------------------------------------------------
// Fused kernel BC: one block per row (704 threads = 1 thread per pixel i).
// Stage 1: row min/max. Stage 2: moment bins (smem atomics, value in reg).
// Stage 3: warps 0/1 select top/bottom-16 while ALL warps compute their
// denominator via the geometric-chain over bins. Stage 4: numerators + store.
// ---------------------------------------------------------------------------
__global__ void __launch_bounds__(HW)
kBC(float* __restrict__ out) {
    __shared__ float sv[HW], sv2[HW];
    __shared__ float binS0[NB], binS1[NB], binS2[NB], binS3[NB];
    __shared__ float rmin[NWARP], rmax[NWARP];
    __shared__ float ssel[32];
    __shared__ float s_lo, s_W;
    int r = blockIdx.x;
    int tid = threadIdx.x;   // 0..703
    int lane = tid & 31, wid = tid >> 5;

    float bv = g_BL[r * HW + tid];
    float a  = g_X0[r * HW + tid];
    sv[tid] = bv; sv2[tid] = bv;
    if (tid < NB) { binS0[tid] = 0.f; binS1[tid] = 0.f; binS2[tid] = 0.f; binS3[tid] = 0.f; }

    // warp min/max -> block min/max
    float lmin = bv, lmax = bv;
#pragma unroll
    for (int o = 16; o; o >>= 1) {
        lmin = fminf(lmin, __shfl_xor_sync(0xffffffffu, lmin, o));
        lmax = fmaxf(lmax, __shfl_xor_sync(0xffffffffu, lmax, o));
    }
    if (lane == 0) { rmin[wid] = lmin; rmax[wid] = lmax; }
    __syncthreads();
    if (tid == 0) {
        float lo = rmin[0], hi = rmax[0];
#pragma unroll
        for (int w = 1; w < NWARP; w++) { lo = fminf(lo, rmin[w]); hi = fmaxf(hi, rmax[w]); }
        s_lo = lo;
        s_W  = (hi - lo) * (1.0f / NB) + 1e-30f;
    }
    __syncthreads();

    float lo = s_lo, W = s_W, invW = 1.0f / W;
    {
        int m = (int)((bv - lo) * invW);
        m = (m > NB - 1) ? NB - 1 : (m < 0 ? 0 : m);
        float d = bv - fmaf((float)m + 0.5f, W, lo);
        atomicAdd(&binS0[m], 1.0f);
        atomicAdd(&binS1[m], d);
        atomicAdd(&binS2[m], 0.5f * d * d);
        atomicAdd(&binS3[m], (1.0f / 6.0f) * d * d * d);
    }
    __syncthreads();   // bins ready; sv/sv2 stable since fill

    // warps 0/1: top/bottom-16 selection (consumes sv / sv2)
    if (wid == 0) {
        for (int it = 0; it < TOPK; it++) {
            float lm = -CUDART_INF_F; int li = 0;
            for (int j = lane; j < HW; j += 32) {
                float v = sv[j];
                if (v > lm) { lm = v; li = j; }
            }
#pragma unroll
            for (int o = 16; o; o >>= 1) {
                float ov = __shfl_xor_sync(0xffffffffu, lm, o);
                int   oi = __shfl_xor_sync(0xffffffffu, li, o);
                if (ov > lm || (ov == lm && oi < li)) { lm = ov; li = oi; }
            }
            if (lane == 0) { ssel[it] = lm; sv[li] = -CUDART_INF_F; }
            __syncwarp();
        }
    } else if (wid == 1) {
        for (int it = 0; it < TOPK; it++) {
            float lm = CUDART_INF_F; int li = 0;
            for (int j = lane; j < HW; j += 32) {
                float v = sv2[j];
                if (v < lm) { lm = v; li = j; }
            }
#pragma unroll
            for (int o = 16; o; o >>= 1) {
                float ov = __shfl_xor_sync(0xffffffffu, lm, o);
                int   oi = __shfl_xor_sync(0xffffffffu, li, o);
                if (ov < lm || (ov == lm && oi < li)) { lm = ov; li = oi; }
            }
            if (lane == 0) { ssel[16 + it] = lm; sv2[li] = CUDART_INF_F; }
            __syncwarp();
        }
    }

    // ALL warps: denominator via geometric chain over bins (overlaps selection)
    bool pos = (a >= 0.f);
    int mask = pos ? (NB - 1) : 0;
    float cs = pos ? fmaf((float)NB - 0.5f, W, lo) : fmaf(0.5f, W, lo);
    // exponent reference: hi for pos, lo for neg (endpoints, not yet top-1;
    // chain from cs which is within 0.5W of the true max score exponent)
    float rho = ex2(-fabsf(a) * W);                 // <= 1, decaying chain
    float rho4 = rho * rho; rho4 *= rho4;
    float p0 = 1.0f;                                // start at dominant bin center
    float p1 = p0 * rho, p2 = p1 * rho, p3 = p2 * rho;
    float L = a * LN2F;

    float D0 = 0.f, D1 = 0.f, D2 = 0.f, D3 = 0.f;
#pragma unroll 4
    for (int m = 0; m < NB; m += 4) {
        int i0 = (m + 0) ^ mask, i1 = (m + 1) ^ mask;
        int i2 = (m + 2) ^ mask, i3 = (m + 3) ^ mask;
        D0 = fmaf(p0, fmaf(L, fmaf(L, fmaf(L, binS3[i0], binS2[i0]), binS1[i0]), binS0[i0]), D0);
        D1 = fmaf(p1, fmaf(L, fmaf(L, fmaf(L, binS3[i1], binS2[i1]), binS1[i1]), binS0[i1]), D1);
        D2 = fmaf(p2, fmaf(L, fmaf(L, fmaf(L, binS3[i2], binS2[i2]), binS1[i2]), binS0[i2]), D2);
        D3 = fmaf(p3, fmaf(L, fmaf(L, fmaf(L, binS3[i3], binS2[i3]), binS1[i3]), binS0[i3]), D3);
        p0 *= rho4; p1 *= rho4; p2 *= rho4; p3 *= rho4;
    }
    float Dref = (D0 + D1) + (D2 + D3);   // = sum exp2(a*bl_j - a*cs)

    __syncthreads();   // ssel ready

    // numerators: exp2(a*sel_k - a*cs) / Dref  (same reference cs cancels)
    float nm = -(pos ? a * cs : a * cs);
    float rD = __frcp_rn(Dref);
    const float* sel = pos ? ssel : (ssel + 16);
    float v[TOPK];
#pragma unroll
    for (int k = 0; k < TOPK; k++)
        v[k] = ex2(fmaf(a, sel[k], nm)) * rD;

    // output: idx = i*16 + k ; k2 = i/44 (k-independent)
    int i  = tid;
    int n  = r / (S_FR - 1);
    int sp = r - n * (S_FR - 1);
    int k2 = i / 44;
    int im = i - k2 * 44;
    float4* o = reinterpret_cast<float4*>(
        out + ((size_t)((n * TOPK + k2) * (S_FR - 1) + sp)) * HW + im * 16);
    o[0] = make_float4(v[0],  v[1],  v[2],  v[3]);
    o[1] = make_float4(v[4],  v[5],  v[6],  v[7]);
    o[2] = make_float4(v[8],  v[9],  v[10], v[11]);
    o[3] = make_float4(v[12], v[13], v[14], v[15]);
}

// ---------------------------------------------------------------------------
extern "C" void kernel_launch(void* const* d_in, const int* in_sizes, int n_in,
                              void* d_out, int out_size) {
    const float* x  = (const float*)d_in[0];
    const float* w1 = (const float*)d_in[1];
    const float* b1 = (const float*)d_in[2];
    const float* w2 = (const float*)d_in[3];
    const float* b2 = (const float*)d_in[4];
    float* out = (float*)d_out;

    kA<<<NPIX / 64, 128>>>(x, w1, b1, w2, b2);
    kBC<<<NS, HW>>>(out);
}

// round 8
// speedup vs baseline: 1.8386x; 1.1825x over previous
#include <cuda_runtime.h>
#include <math_constants.h>

// Problem constants
#define N_BATCH 4
#define C_CH    128
#define S_FR    31
#define HW      704           // 32*22
#define NS      120           // 4*(31-1)
#define NPIX    87296         // 4*31*704 (= 64*1364)
#define TOPK    16
#define NB      64            // denominator bins (power of 2)
#define NWARP   22            // 704/32
#define LOG2E   1.4426950408889634f
#define LN2F    0.6931471805599453f

// Scratch (device globals — no allocation allowed)
__device__ float g_X0[NS * HW];        // a values
__device__ float g_BL[NS * HW];        // b * log2e (order-preserving)

__device__ __forceinline__ float ex2(float x) {
    float r;
    asm("ex2.approx.f32 %0, %1;" : "=f"(r) : "f"(x));
    return r;
}

// ---------------------------------------------------------------------------
// Kernel A (R3 winner, verbatim): channel contraction, 2 threads per pixel.
// ---------------------------------------------------------------------------
__global__ void kA(const float* __restrict__ x,
                   const float* __restrict__ w1, const float* __restrict__ b1,
                   const float* __restrict__ w2, const float* __restrict__ b2) {
    __shared__ float sw1[C_CH], sw2[C_CH];
    __shared__ float r1s[64], r2s[64];
    int tid = threadIdx.x;          // 0..127
    sw1[tid] = w1[tid];
    sw2[tid] = w2[tid];
    __syncthreads();

    int half = tid >> 6;            // 0 or 1
    int px   = tid & 63;
    int p = blockIdx.x * 64 + px;   // NPIX = 64*1364 exactly
    int n = p / (S_FR * HW);
    int q = p - n * (S_FR * HW);
    int f = q / HW;
    int i = q - f * HW;

    const float* xp = x + (size_t)n * (C_CH * S_FR * HW)
                        + (size_t)(half * 64) * (S_FR * HW) + q;
    const float* pw1 = sw1 + half * 64;
    const float* pw2 = sw2 + half * 64;

    float y1a = 0.f, y1b = 0.f, y2a = 0.f, y2b = 0.f;
#pragma unroll
    for (int cb = 0; cb < 64; cb += 16) {
        float v[16];
#pragma unroll
        for (int u = 0; u < 16; u++) v[u] = xp[(cb + u) * (S_FR * HW)];
#pragma unroll
        for (int u = 0; u < 16; u += 2) {
            y1a = fmaf(v[u],     pw1[cb + u],     y1a);
            y2a = fmaf(v[u],     pw2[cb + u],     y2a);
            y1b = fmaf(v[u + 1], pw1[cb + u + 1], y1b);
            y2b = fmaf(v[u + 1], pw2[cb + u + 1], y2b);
        }
    }
    float y1 = y1a + y1b, y2 = y2a + y2b;

    if (half == 1) { r1s[px] = y1; r2s[px] = y2; }
    __syncthreads();
    if (half == 0) {
        y1 += r1s[px];
        y2 += r2s[px];
        if (f < S_FR - 1) g_X0[(n * (S_FR - 1) + f) * HW + i] = y1 + b1[0];
        if (f >= 1)       g_BL[(n * (S_FR - 1) + f - 1) * HW + i] = (y2 + b2[0]) * LOG2E;
    }
}

// ---------------------------------------------------------------------------
// Fused kernel BC. One block per row, 704 threads.
// Selection via histogram-threshold candidate gather + warp bitonic sort
// (fallback: iterative). Denominator: geometric chain over NB=64 float4 bins.
// ---------------------------------------------------------------------------
__global__ void __launch_bounds__(HW)
kBC(float* __restrict__ out) {
    __shared__ float  sv[HW], sv2[HW];          // fallback-only consumable copies
    __shared__ float4 sbin[NB];                 // (S0, S1, S2/2, S3/6)
    __shared__ float  rmin[NWARP], rmax[NWARP];
    __shared__ float  ssel[32];
    __shared__ float  s_lo, s_W;
    __shared__ int    s_ttop, s_tbot, s_fbtop, s_fbbot;
    __shared__ int    s_ctop, s_cbot;
    __shared__ float  candT[32], candB[32];

    int r = blockIdx.x;
    int tid = threadIdx.x;   // 0..703
    int lane = tid & 31, wid = tid >> 5;
    float* binsf = reinterpret_cast<float*>(sbin);

    float bv = g_BL[r * HW + tid];
    float a  = g_X0[r * HW + tid];
    sv[tid] = bv; sv2[tid] = bv;
    if (tid < NB) sbin[tid] = make_float4(0.f, 0.f, 0.f, 0.f);
    if (tid == 704 - 1) { s_ctop = 0; s_cbot = 0; }

    // warp min/max
    float lmin = bv, lmax = bv;
#pragma unroll
    for (int o = 16; o; o >>= 1) {
        lmin = fminf(lmin, __shfl_xor_sync(0xffffffffu, lmin, o));
        lmax = fmaxf(lmax, __shfl_xor_sync(0xffffffffu, lmax, o));
    }
    if (lane == 0) { rmin[wid] = lmin; rmax[wid] = lmax; }
    __syncthreads();
    if (tid == 0) {
        float lo = rmin[0], hi = rmax[0];
#pragma unroll
        for (int w = 1; w < NWARP; w++) { lo = fminf(lo, rmin[w]); hi = fmaxf(hi, rmax[w]); }
        s_lo = lo;
        s_W  = (hi - lo) * (1.0f / NB) + 1e-30f;
    }
    __syncthreads();

    float lo = s_lo, W = s_W, invW = 1.0f / W;
    int m;
    {
        m = (int)((bv - lo) * invW);
        m = (m > NB - 1) ? NB - 1 : (m < 0 ? 0 : m);
        float d = bv - fmaf((float)m + 0.5f, W, lo);
        float* bp = binsf + 4 * m;
        atomicAdd(bp + 0, 1.0f);
        atomicAdd(bp + 1, d);
        atomicAdd(bp + 2, 0.5f * d * d);
        atomicAdd(bp + 3, (1.0f / 6.0f) * d * d * d);
    }
    __syncthreads();

    // thresholds from histogram counts (warps 0 and 1)
    if (wid == 0) {
        // lane l owns bins 2l, 2l+1; suffix sums (from high bins down)
        float c0 = binsf[(2 * lane) * 4];
        float c1 = binsf[(2 * lane + 1) * 4];
        float suf = c0 + c1;
#pragma unroll
        for (int o = 1; o < 32; o <<= 1) {
            float v = __shfl_down_sync(0xffffffffu, suf, o);
            if (lane + o < 32) suf += v;
        }
        float Seven = suf;              // S(2l)
        float Sodd  = suf - c0;         // S(2l+1)
        int best = -1;
        if (Sodd  >= 16.f) best = 2 * lane + 1;
        else if (Seven >= 16.f) best = 2 * lane;
        float Sb = (best == 2 * lane + 1) ? Sodd : ((best == 2 * lane) ? Seven : 0.f);
#pragma unroll
        for (int o = 16; o; o >>= 1) {
            int   ob = __shfl_xor_sync(0xffffffffu, best, o);
            float os = __shfl_xor_sync(0xffffffffu, Sb, o);
            if (ob > best) { best = ob; Sb = os; }
        }
        if (lane == 0) { s_ttop = best; s_fbtop = (Sb > 32.f) ? 1 : 0; }
    } else if (wid == 1) {
        // prefix sums (from low bins up)
        float c0 = binsf[(2 * lane) * 4];
        float c1 = binsf[(2 * lane + 1) * 4];
        float pre = c0 + c1;
#pragma unroll
        for (int o = 1; o < 32; o <<= 1) {
            float v = __shfl_up_sync(0xffffffffu, pre, o);
            if (lane >= o) pre += v;
        }
        float Podd  = pre;              // P(2l+1)
        float Peven = pre - c1;         // P(2l)
        int best = 0x7fffffff;
        if (Peven >= 16.f) best = 2 * lane;
        else if (Podd >= 16.f) best = 2 * lane + 1;
        float Pb = (best == 2 * lane) ? Peven : ((best == 2 * lane + 1) ? Podd : 0.f);
#pragma unroll
        for (int o = 16; o; o >>= 1) {
            int   ob = __shfl_xor_sync(0xffffffffu, best, o);
            float os = __shfl_xor_sync(0xffffffffu, Pb, o);
            if (ob < best) { best = ob; Pb = os; }
        }
        if (lane == 0) { s_tbot = best; s_fbbot = (Pb > 32.f) ? 1 : 0; }
    }
    __syncthreads();

    // candidate gather (all threads; counts guaranteed <= 32 when no fallback)
    if (!s_fbtop && m >= s_ttop) candT[atomicAdd(&s_ctop, 1)] = bv;
    if (!s_fbbot && m <= s_tbot) candB[atomicAdd(&s_cbot, 1)] = bv;
    __syncthreads();

    // selection: warp 0 top-16 desc, warp 1 bottom-16 asc
    if (wid == 0) {
        if (!s_fbtop) {
            float v = (lane < s_ctop) ? candT[lane] : -CUDART_INF_F;
#pragma unroll
            for (int k = 2; k <= 32; k <<= 1) {
#pragma unroll
                for (int j = k >> 1; j > 0; j >>= 1) {
                    float o = __shfl_xor_sync(0xffffffffu, v, j);
                    bool up = ((lane & k) == 0);
                    bool keepMin = (((lane & j) == 0) == up);
                    v = keepMin ? fminf(v, o) : fmaxf(v, o);
                }
            }
            // ascending across lanes; top-16 desc = lanes 31..16
            if (lane >= 16) ssel[31 - lane] = v;
        } else {
            for (int it = 0; it < TOPK; it++) {
                float lm = -CUDART_INF_F; int li = 0;
                for (int j = lane; j < HW; j += 32) {
                    float v = sv[j];
                    if (v > lm) { lm = v; li = j; }
                }
#pragma unroll
                for (int o = 16; o; o >>= 1) {
                    float ov = __shfl_xor_sync(0xffffffffu, lm, o);
                    int   oi = __shfl_xor_sync(0xffffffffu, li, o);
                    if (ov > lm || (ov == lm && oi < li)) { lm = ov; li = oi; }
                }
                if (lane == 0) { ssel[it] = lm; sv[li] = -CUDART_INF_F; }
                __syncwarp();
            }
        }
    } else if (wid == 1) {
        if (!s_fbbot) {
            float v = (lane < s_cbot) ? candB[lane] : CUDART_INF_F;
#pragma unroll
            for (int k = 2; k <= 32; k <<= 1) {
#pragma unroll
                for (int j = k >> 1; j > 0; j >>= 1) {
                    float o = __shfl_xor_sync(0xffffffffu, v, j);
                    bool up = ((lane & k) == 0);
                    bool keepMin = (((lane & j) == 0) == up);
                    v = keepMin ? fminf(v, o) : fmaxf(v, o);
                }
            }
            // ascending; bottom-16 asc = lanes 0..15
            if (lane < 16) ssel[16 + lane] = v;
        } else {
            for (int it = 0; it < TOPK; it++) {
                float lm = CUDART_INF_F; int li = 0;
                for (int j = lane; j < HW; j += 32) {
                    float v = sv2[j];
                    if (v < lm) { lm = v; li = j; }
                }
#pragma unroll
                for (int o = 16; o; o >>= 1) {
                    float ov = __shfl_xor_sync(0xffffffffu, lm, o);
                    int   oi = __shfl_xor_sync(0xffffffffu, li, o);
                    if (ov < lm || (ov == lm && oi < li)) { lm = ov; li = oi; }
                }
                if (lane == 0) { ssel[16 + it] = lm; sv2[li] = CUDART_INF_F; }
                __syncwarp();
            }
        }
    }

    // ALL warps: denominator via geometric chain over bins
    bool pos = (a >= 0.f);
    int mask = pos ? (NB - 1) : 0;
    float cs = pos ? fmaf((float)NB - 0.5f, W, lo) : fmaf(0.5f, W, lo);

    float rho = ex2(-fabsf(a) * W);                 // <= 1, decaying chain
    float rho4 = rho * rho; rho4 *= rho4;
    float p0 = 1.0f;
    float p1 = rho, p2 = rho * rho, p3 = p2 * rho;
    float L = a * LN2F;

    float D0 = 0.f, D1 = 0.f, D2 = 0.f, D3 = 0.f;
#pragma unroll 4
    for (int mm = 0; mm < NB; mm += 4) {
        float4 c0 = sbin[(mm + 0) ^ mask];
        float4 c1 = sbin[(mm + 1) ^ mask];
        float4 c2 = sbin[(mm + 2) ^ mask];
        float4 c3 = sbin[(mm + 3) ^ mask];
        D0 = fmaf(p0, fmaf(L, fmaf(L, fmaf(L, c0.w, c0.z), c0.y), c0.x), D0);
        D1 = fmaf(p1, fmaf(L, fmaf(L, fmaf(L, c1.w, c1.z), c1.y), c1.x), D1);
        D2 = fmaf(p2, fmaf(L, fmaf(L, fmaf(L, c2.w, c2.z), c2.y), c2.x), D2);
        D3 = fmaf(p3, fmaf(L, fmaf(L, fmaf(L, c3.w, c3.z), c3.y), c3.x), D3);
        p0 *= rho4; p1 *= rho4; p2 *= rho4; p3 *= rho4;
    }
    float Dref = (D0 + D1) + (D2 + D3);   // = sum exp2(a*bl_j - a*cs)

    __syncthreads();   // ssel ready

    float nm = -a * cs;
    float rD = __frcp_rn(Dref);
    const float* sel = pos ? ssel : (ssel + 16);
    float v[TOPK];
#pragma unroll
    for (int k = 0; k < TOPK; k++)
        v[k] = ex2(fmaf(a, sel[k], nm)) * rD;

    // output: idx = i*16 + k ; k2 = i/44 (k-independent)
    int i  = tid;
    int n  = r / (S_FR - 1);
    int sp = r - n * (S_FR - 1);
    int k2 = i / 44;
    int im = i - k2 * 44;
    float4* o = reinterpret_cast<float4*>(
        out + ((size_t)((n * TOPK + k2) * (S_FR - 1) + sp)) * HW + im * 16);
    o[0] = make_float4(v[0],  v[1],  v[2],  v[3]);
    o[1] = make_float4(v[4],  v[5],  v[6],  v[7]);
    o[2] = make_float4(v[8],  v[9],  v[10], v[11]);
    o[3] = make_float4(v[12], v[13], v[14], v[15]);
}

// ---------------------------------------------------------------------------
extern "C" void kernel_launch(void* const* d_in, const int* in_sizes, int n_in,
                              void* d_out, int out_size) {
    const float* x  = (const float*)d_in[0];
    const float* w1 = (const float*)d_in[1];
    const float* b1 = (const float*)d_in[2];
    const float* w2 = (const float*)d_in[3];
    const float* b2 = (const float*)d_in[4];
    float* out = (float*)d_out;

    kA<<<NPIX / 64, 128>>>(x, w1, b1, w2, b2);
    kBC<<<NS, HW>>>(out);
}